// round 12
// baseline (speedup 1.0000x reference)
#include <cuda_runtime.h>
#include <math.h>

#define CIN 64
#define HW  256
#define HO  128
#define NB  16

// ---------------- device scratch (no allocations allowed) ----------------
__device__ float g_pooled[NB * CIN];
__device__ int   g_selidx[NB * 2];
__device__ float g_selwt [NB * 2];
__device__ int   g_sched [NB * 2];   // block order: heavy experts first
__device__ float g_bnA[4 * 64];
__device__ float g_bnB[4 * 64];
// transposed weights [e][cin][kh][kw][cout], cout minor
// sizes: e0 36864, e1 102400, e2 200704, e3 331776 -> total 671744
__device__ float g_wT[671744];
// zero page: out-of-bounds taps point here (covers cl*65536 offsets, CHUNK<=16)
__device__ float g_zero[1048576];    // 4 MB, zero-initialized at module load

// ---------------- launch #1: global average pool, one block per (b,c) plane ----
__global__ void pool_kernel(const float* __restrict__ x) {
    __shared__ float red[256];
    int tid = threadIdx.x;
    const float4* xp = (const float4*)(x + (size_t)blockIdx.x * (HW * HW));
    float s = 0.f;
    for (int i = tid; i < HW * HW / 4; i += 256) {
        float4 v = xp[i];
        s += (v.x + v.y) + (v.z + v.w);
    }
    red[tid] = s;
    __syncthreads();
    for (int off = 128; off > 0; off >>= 1) {
        if (tid < off) red[tid] += red[tid + off];
        __syncthreads();
    }
    if (tid == 0) g_pooled[blockIdx.x] = red[0] * (1.f / (HW * HW));
}

// ---------------- launch #2: ALL weight transposes in one kernel ----------------
__device__ __forceinline__ void twk_one(const float* __restrict__ w, int off, int KK, int i) {
    int cout = i & 63;
    int row  = i >> 6;
    int cin  = row / KK;
    int kidx = row - cin * KK;
    g_wT[off + i] = w[(cout * 64 + cin) * KK + kidx];
}

__global__ void twk_all_kernel(const float* __restrict__ w0, const float* __restrict__ w1,
                               const float* __restrict__ w2, const float* __restrict__ w3) {
    int i = blockIdx.x * 256 + threadIdx.x;
    if (i < 36864)       twk_one(w0, 0,      9,  i);
    else if (i < 139264) twk_one(w1, 36864,  25, i - 36864);
    else if (i < 339968) twk_one(w2, 139264, 49, i - 139264);
    else if (i < 671744) twk_one(w3, 339968, 81, i - 339968);
}

// ---------------- launch #3: gate (softmax + top-2 + schedule) AND bn fold ------
__global__ void gatebn_kernel(const float* __restrict__ gw, const float* __restrict__ gb,
                              const float* __restrict__ sc, const float* __restrict__ bi,
                              const float* __restrict__ me, const float* __restrict__ va,
                              const float* __restrict__ b0, const float* __restrict__ b1,
                              const float* __restrict__ b2, const float* __restrict__ b3) {
    __shared__ int s_idx[NB * 2];
    int t = threadIdx.x;

    // BN fold: y = conv*A + B  (256 threads = 4 experts x 64 couts)
    {
        const float* bb = (t < 64) ? b0 : (t < 128) ? b1 : (t < 192) ? b2 : b3;
        float inv = sc[t] * rsqrtf(va[t] + 1e-5f);
        g_bnA[t] = inv;
        g_bnB[t] = bb[t & 63] * inv + bi[t] - me[t] * inv;
    }

    // Gate (threads 0..15, one per batch)
    if (t < NB) {
        int b = t;
        float lg[4];
        for (int e = 0; e < 4; ++e) {
            float s = gb[e];
            for (int c = 0; c < CIN; ++c) s += g_pooled[b * CIN + c] * gw[e * CIN + c];
            lg[e] = s;
        }
        float m = fmaxf(fmaxf(lg[0], lg[1]), fmaxf(lg[2], lg[3]));
        float p[4];
        float Z = 0.f;
        for (int e = 0; e < 4; ++e) { p[e] = expf(lg[e] - m); Z += p[e]; }
        for (int e = 0; e < 4; ++e) p[e] /= Z;
        int i0 = 0;
        for (int e = 1; e < 4; ++e) if (p[e] > p[i0]) i0 = e;   // strict >, lower idx wins ties
        int i1 = -1;
        for (int e = 0; e < 4; ++e) {
            if (e == i0) continue;
            if (i1 < 0 || p[e] > p[i1]) i1 = e;
        }
        float den = p[i0] + p[i1] + 1e-8f;
        g_selidx[b * 2 + 0] = i0; g_selwt[b * 2 + 0] = p[i0] / den;
        g_selidx[b * 2 + 1] = i1; g_selwt[b * 2 + 1] = p[i1] / den;
        s_idx[b * 2 + 0] = i0;
        s_idx[b * 2 + 1] = i1;
    }
    __syncthreads();
    if (t == 0) {
        // stable counting sort, heaviest expert (largest K) first
        int n = 0;
        for (int e = 3; e >= 0; --e)
            for (int z = 0; z < NB * 2; ++z)
                if (s_idx[z] == e) g_sched[n++] = z;
    }
}

// single-MOV duplication: LDG lands in the pair's lo half, one MOV fills hi
__device__ __forceinline__ unsigned long long pack_dup(float v) {
    float2 f;
    f.x = v;
    f.y = v;
    return *reinterpret_cast<unsigned long long*>(&f);
}

// ---------------- launch #4: merged expert conv + BN + GELU, packed f32x2 FMA ---
// TAP-OUTER, PREDICATE-FREE MAINLOOP, BIG-CHUNK DYNAMIC SMEM:
// 256 threads = 32(ow) x 4(cout-quarter:16 couts) x 2(row groups);
// each thread 4 oh-rows x 16 couts => 4x8 u64 acc (64 regs) -> 2 blocks/SM.
// Boundary handled ONCE per tap by pointer select (valid ? &x[...] : g_zero);
// inner cin-chunk loop is pure LDG + 1-MOV pack + broadcast LDS.128 + 32xFFMA2.
// CHUNK: E0 16, E1 16, E2 8, E3 4 (100KB dynamic smem, 2 blocks/SM).
template <int E, int K, int D, int CHUNK, int WOFF>
__device__ __forceinline__ void conv_body(const float* __restrict__ xb,
                                          float* __restrict__ out,
                                          int z, int tid, float4* sw4) {
    const int pad = D * (K - 1) / 2;
    const int owl = tid & 31;
    const int chq = (tid >> 5) & 3;              // 4 groups of 16 couts
    const int ohq = tid >> 7;                    // 2 groups of 4 rows
    const int ow  = blockIdx.x * 32 + owl;
    const int oh0 = blockIdx.y * 8 + ohq * 4;    // 4 rows per thread
    const int ows = 2 * ow - pad;

    int ohs[4];
    unsigned rmask[4];
#pragma unroll
    for (int p = 0; p < 4; ++p) {
        ohs[p] = 2 * (oh0 + p) - pad;
        unsigned m = 0;
#pragma unroll
        for (int k = 0; k < K; ++k)
            if ((unsigned)(ohs[p] + D * k) < (unsigned)HW) m |= 1u << k;
        rmask[p] = m;
    }
    unsigned cmask = 0;
#pragma unroll
    for (int k = 0; k < K; ++k)
        if ((unsigned)(ows + D * k) < (unsigned)HW) cmask |= 1u << k;

    unsigned long long acc[4][8];
#pragma unroll
    for (int p = 0; p < 4; ++p)
#pragma unroll
        for (int r = 0; r < 8; ++r) acc[p][r] = 0ULL;

    float* sw = (float*)sw4;
    const float4* wsrc = (const float4*)(g_wT + WOFF);

    for (int cc = 0; cc < CIN; cc += CHUNK) {
        __syncthreads();
        for (int i = tid; i < CHUNK * K * K * 16; i += 256)
            sw4[i] = wsrc[cc * (K * K * 16) + i];
        __syncthreads();

        // base of this chunk's x planes
        const float* xc = xb + (size_t)cc * (HW * HW);

#pragma unroll 1
        for (int kh = 0; kh < K; ++kh) {
            const float* xrow[4];
            bool rv[4];
#pragma unroll
            for (int p = 0; p < 4; ++p) {
                xrow[p] = xc + (ohs[p] + D * kh) * HW + ows;   // may be wild; gated below
                rv[p] = (rmask[p] >> kh) & 1;
            }
#pragma unroll
            for (int kw = 0; kw < K; ++kw) {
                const bool cv = (cmask >> kw) & 1;
                // one pointer select per pixel per tap; g_zero covers cl*65536 offsets
                const float* xq[4];
#pragma unroll
                for (int p = 0; p < 4; ++p)
                    xq[p] = (rv[p] && cv) ? (xrow[p] + D * kw) : g_zero;
                const float* wk = sw + (kh * K + kw) * 64 + chq * 16;
                // ---- pure LDG + 1-MOV pack + LDS.128 + FFMA2 over the cin chunk ----
#pragma unroll
                for (int cl = 0; cl < CHUNK; ++cl) {
                    unsigned long long x2[4];
#pragma unroll
                    for (int p = 0; p < 4; ++p)
                        x2[p] = pack_dup(__ldg(xq[p] + cl * (HW * HW)));
                    const ulonglong2* wq =
                        (const ulonglong2*)(wk + cl * (K * K * 64));
#pragma unroll
                    for (int q = 0; q < 4; ++q) {
                        ulonglong2 wv = wq[q];
#pragma unroll
                        for (int p = 0; p < 4; ++p) {
                            asm("fma.rn.f32x2 %0, %1, %2, %0;"
                                : "+l"(acc[p][2 * q + 0]) : "l"(x2[p]), "l"(wv.x));
                            asm("fma.rn.f32x2 %0, %1, %2, %0;"
                                : "+l"(acc[p][2 * q + 1]) : "l"(x2[p]), "l"(wv.y));
                        }
                    }
                }
            }
        }
    }

    // epilogue: BN fold + exact GELU + gate weight; stores coalesced along ow
    const float wt = g_selwt[z];
    const int b = z >> 1, s = z & 1;
#pragma unroll
    for (int p = 0; p < 4; ++p) {
        float* ob = out + ((size_t)b * 128 + s * 64 + chq * 16) * (HO * HO)
                  + (oh0 + p) * HO + ow;
#pragma unroll
        for (int r = 0; r < 8; ++r) {
            unsigned u0, u1;
            asm("mov.b64 {%0, %1}, %2;" : "=r"(u0), "=r"(u1) : "l"(acc[p][r]));
            float v0 = __uint_as_float(u0);
            float v1 = __uint_as_float(u1);
            const int c0 = chq * 16 + 2 * r, c1 = c0 + 1;
            float y0 = v0 * g_bnA[E * 64 + c0] + g_bnB[E * 64 + c0];
            float y1 = v1 * g_bnA[E * 64 + c1] + g_bnB[E * 64 + c1];
            y0 = 0.5f * y0 * (1.f + erff(y0 * 0.70710678118654752f));
            y1 = 0.5f * y1 * (1.f + erff(y1 * 0.70710678118654752f));
            ob[(size_t)(2 * r) * (HO * HO)]     = y0 * wt;
            ob[(size_t)(2 * r + 1) * (HO * HO)] = y1 * wt;
        }
    }
}

// dynamic smem: max = E1 CHUNK=16 -> 16*25*64 floats = 102400 bytes
// (E2 CHUNK=8 -> 100352 B, E3 CHUNK=4 -> 82944 B, E0 CHUNK=16 -> 36864 B)
// 2 blocks x 102400 = 204800 B <= 228KB/SM => occupancy 2 preserved
#define CONV_SMEM_BYTES 102400

__global__ void __launch_bounds__(256, 2)
conv_all_kernel(const float* __restrict__ x, float* __restrict__ out) {
    extern __shared__ float4 sw4[];
    const int z = g_sched[blockIdx.z];          // heavy-first schedule
    const int tid = threadIdx.x;
    const float* xb = x + (size_t)(z >> 1) * CIN * HW * HW;
    const int e = g_selidx[z];
    if (e == 0)      conv_body<0, 3, 1, 16, 0     >(xb, out, z, tid, sw4);
    else if (e == 1) conv_body<1, 5, 2, 16, 36864 >(xb, out, z, tid, sw4);
    else if (e == 2) conv_body<2, 7, 3, 8,  139264>(xb, out, z, tid, sw4);
    else             conv_body<3, 9, 4, 4,  339968>(xb, out, z, tid, sw4);
}

// ---------------- launch: exactly 4 launches, conv is #4 (ncu capture slot) -----
extern "C" void kernel_launch(void* const* d_in, const int* in_sizes, int n_in,
                              void* d_out, int out_size) {
    (void)in_sizes; (void)n_in; (void)out_size;
    const float* x   = (const float*)d_in[0];
    const float* w0  = (const float*)d_in[1];
    const float* b0  = (const float*)d_in[2];
    const float* w1  = (const float*)d_in[3];
    const float* b1  = (const float*)d_in[4];
    const float* w2  = (const float*)d_in[5];
    const float* b2  = (const float*)d_in[6];
    const float* w3  = (const float*)d_in[7];
    const float* b3  = (const float*)d_in[8];
    const float* bns = (const float*)d_in[9];
    const float* bnb = (const float*)d_in[10];
    const float* bnm = (const float*)d_in[11];
    const float* bnv = (const float*)d_in[12];
    const float* gw  = (const float*)d_in[13];
    const float* gb  = (const float*)d_in[14];
    float* out = (float*)d_out;

    static int s_attr_set = 0;
    if (!s_attr_set) {
        cudaFuncSetAttribute(conv_all_kernel,
                             cudaFuncAttributeMaxDynamicSharedMemorySize,
                             CONV_SMEM_BYTES);
        s_attr_set = 1;
    }

    pool_kernel<<<NB * CIN, 256>>>(x);                               // #1
    twk_all_kernel<<<(671744 + 255) / 256, 256>>>(w0, w1, w2, w3);   // #2
    gatebn_kernel<<<1, 256>>>(gw, gb, bns, bnb, bnm, bnv,
                              b0, b1, b2, b3);                       // #3
    dim3 grid(4, 16, NB * 2);  // 128/32 ow-tiles x 128/8 oh-tiles x (b,slot)
    conv_all_kernel<<<grid, 256, CONV_SMEM_BYTES>>>(x, out);         // #4
}

// round 14
// speedup vs baseline: 1.7347x; 1.7347x over previous
#include <cuda_runtime.h>
#include <cuda_bf16.h>
#include <math.h>

#define CIN 64
#define HW  256
#define HO  128
#define NB  16

// ---------------- device scratch (no allocations allowed) ----------------
__device__ float g_pooled[NB * CIN];
__device__ int   g_selidx[NB * 2];
__device__ float g_selwt [NB * 2];
__device__ int   g_sched [NB * 2];
__device__ float g_bnA[4 * 64];
__device__ float g_bnB[4 * 64];
// split weights: [split(2)][tapflat(164)][cout(64)][cin(64)] bf16
// tap offsets: E0:0(9), E1:9(25), E2:34(49), E3:83(81) -> 164 taps
__device__ __align__(16) __nv_bfloat16 g_wS[2 * 164 * 4096];

// ---------------- launch #1: global average pool ----------------
__global__ void pool_kernel(const float* __restrict__ x) {
    __shared__ float red[256];
    int tid = threadIdx.x;
    const float4* xp = (const float4*)(x + (size_t)blockIdx.x * (HW * HW));
    float s = 0.f;
    for (int i = tid; i < HW * HW / 4; i += 256) {
        float4 v = xp[i];
        s += (v.x + v.y) + (v.z + v.w);
    }
    red[tid] = s;
    __syncthreads();
    for (int off = 128; off > 0; off >>= 1) {
        if (tid < off) red[tid] += red[tid + off];
        __syncthreads();
    }
    if (tid == 0) g_pooled[blockIdx.x] = red[0] * (1.f / (HW * HW));
}

// ---------------- launch #2: weight split to bf16 hi/lo ----------------
__global__ void wsplit_kernel(const float* __restrict__ w0, const float* __restrict__ w1,
                              const float* __restrict__ w2, const float* __restrict__ w3) {
    int i = blockIdx.x * 256 + threadIdx.x;
    if (i >= 164 * 4096) return;
    int cin  = i & 63;
    int cout = (i >> 6) & 63;
    int tapf = i >> 12;
    const float* w; int KK, kidx;
    if (tapf < 9)       { w = w0; KK = 9;  kidx = tapf; }
    else if (tapf < 34) { w = w1; KK = 25; kidx = tapf - 9; }
    else if (tapf < 83) { w = w2; KK = 49; kidx = tapf - 34; }
    else                { w = w3; KK = 81; kidx = tapf - 83; }
    float v = w[(cout * 64 + cin) * KK + kidx];
    __nv_bfloat16 hi = __float2bfloat16(v);
    __nv_bfloat16 lo = __float2bfloat16(v - __bfloat162float(hi));
    g_wS[i] = hi;
    g_wS[671744 + i] = lo;
}

// ---------------- launch #3: gate + bn fold + schedule ----------------
__global__ void gatebn_kernel(const float* __restrict__ gw, const float* __restrict__ gb,
                              const float* __restrict__ sc, const float* __restrict__ bi,
                              const float* __restrict__ me, const float* __restrict__ va,
                              const float* __restrict__ b0, const float* __restrict__ b1,
                              const float* __restrict__ b2, const float* __restrict__ b3) {
    __shared__ int s_idx[NB * 2];
    int t = threadIdx.x;
    {
        const float* bb = (t < 64) ? b0 : (t < 128) ? b1 : (t < 192) ? b2 : b3;
        float inv = sc[t] * rsqrtf(va[t] + 1e-5f);
        g_bnA[t] = inv;
        g_bnB[t] = bb[t & 63] * inv + bi[t] - me[t] * inv;
    }
    if (t < NB) {
        int b = t;
        float lg[4];
        for (int e = 0; e < 4; ++e) {
            float s = gb[e];
            for (int c = 0; c < CIN; ++c) s += g_pooled[b * CIN + c] * gw[e * CIN + c];
            lg[e] = s;
        }
        float m = fmaxf(fmaxf(lg[0], lg[1]), fmaxf(lg[2], lg[3]));
        float p[4]; float Z = 0.f;
        for (int e = 0; e < 4; ++e) { p[e] = expf(lg[e] - m); Z += p[e]; }
        for (int e = 0; e < 4; ++e) p[e] /= Z;
        int i0 = 0;
        for (int e = 1; e < 4; ++e) if (p[e] > p[i0]) i0 = e;
        int i1 = -1;
        for (int e = 0; e < 4; ++e) {
            if (e == i0) continue;
            if (i1 < 0 || p[e] > p[i1]) i1 = e;
        }
        float den = p[i0] + p[i1] + 1e-8f;
        g_selidx[b * 2 + 0] = i0; g_selwt[b * 2 + 0] = p[i0] / den;
        g_selidx[b * 2 + 1] = i1; g_selwt[b * 2 + 1] = p[i1] / den;
        s_idx[b * 2 + 0] = i0;
        s_idx[b * 2 + 1] = i1;
    }
    __syncthreads();
    if (t == 0) {
        int n = 0;
        for (int e = 3; e >= 0; --e)
            for (int z = 0; z < NB * 2; ++z)
                if (s_idx[z] == e) g_sched[n++] = z;
    }
}

// ---------------- mma.sync helpers (sm_80+ ISA, valid on plain sm_100) ----------
__device__ __forceinline__ unsigned smem_u32(const void* p) {
    return (unsigned)__cvta_generic_to_shared(p);
}
__device__ __forceinline__ void sts128(unsigned a, unsigned r0, unsigned r1,
                                       unsigned r2, unsigned r3) {
    asm volatile("st.shared.v4.b32 [%0], {%1,%2,%3,%4};"
                 :: "r"(a), "r"(r0), "r"(r1), "r"(r2), "r"(r3) : "memory");
}
__device__ __forceinline__ void ldsm4(unsigned a, unsigned* r) {
    asm volatile("ldmatrix.sync.aligned.m8n8.x4.shared.b16 {%0,%1,%2,%3}, [%4];"
                 : "=r"(r[0]), "=r"(r[1]), "=r"(r[2]), "=r"(r[3]) : "r"(a));
}
__device__ __forceinline__ void mma16816(float* d, const unsigned* a, const unsigned* b) {
    asm volatile(
        "mma.sync.aligned.m16n8k16.row.col.f32.bf16.bf16.f32 "
        "{%0,%1,%2,%3}, {%4,%5,%6,%7}, {%8,%9}, {%0,%1,%2,%3};"
        : "+f"(d[0]), "+f"(d[1]), "+f"(d[2]), "+f"(d[3])
        : "r"(a[0]), "r"(a[1]), "r"(a[2]), "r"(a[3]), "r"(b[0]), "r"(b[1]));
}

// smem layout (dynamic, 144B-padded rows for LDSM conflict avoidance):
//   rc:  2 splits x 288 rows x 144B = 82944   (x row cache, transposed+split)
//   BS:  2 splits x 64 rows x 144B  = 18432   (per-tap B tile) -- unioned with
//   stg: 64x65 f32 staging (16640)            (transpose staging, same region)
#define RC_SPLIT 41472
#define SM_BS    82944
#define BS_SPLIT 9216
#define CONV_SMEM 101376

// ---------------- launch #4: mma.sync bf16-split implicit conv ----------------
// CTA = (z, oh). D[128 ow x 64 cout] += sum_taps A[128 x 64cin] . W[64cout x 64cin]^T
// 3 split segments (hi.hi + lo.hi + hi.lo), fp32 register accumulators.
// 8 warps = 4 (M strips of 32) x 2 (N halves of 32); per warp 2x4 m16n8 tiles.
template <int E, int K, int D, int TAPBASE>
__device__ void conv_body(const float* __restrict__ xb, float* __restrict__ out,
                          int z, char* smem, unsigned sbase) {
    const int tid = threadIdx.x, lane = tid & 31, wid = tid >> 5;
    const int wm = wid >> 1, wn = wid & 1;
    const int oh = blockIdx.x;
    const int pad = D * (K - 1) / 2;
    const unsigned RCB = sbase, BSB = sbase + SM_BS;
    float* stg = (float*)(smem + SM_BS);

    // zero the horizontal-pad rows (0..15, 272..287) in both splits
    for (int i = tid; i < 576; i += 256) {
        int split = i / 288, rem = i % 288, r = rem / 9, c = rem % 9;
        int rrow = (r < 16) ? r : (256 + r);
        sts128(RCB + split * RC_SPLIT + rrow * 144 + c * 16, 0, 0, 0, 0);
    }

    float d[2][4][4];
#pragma unroll
    for (int mt = 0; mt < 2; ++mt)
#pragma unroll
        for (int nt = 0; nt < 4; ++nt)
#pragma unroll
            for (int c = 0; c < 4; ++c) d[mt][nt][c] = 0.f;

    // ldmatrix lane mappings
    const int row16 = lane & 15;
    const int koffA = (lane >> 4) * 16;
    const int bsel = lane >> 3, brow = lane & 7;
    const int bnt = bsel >> 1;
    const int bko = (bsel & 1) * 16;

#pragma unroll 1
    for (int kh = 0; kh < K; ++kh) {
        int xr = 2 * oh - pad + D * kh;
        if ((unsigned)xr >= (unsigned)HW) continue;   // vertical OOB => zero tap row

        // ---- rebuild row cache: transpose + bf16 split, 4 slabs of 64 cols ----
#pragma unroll 1
        for (int slab = 0; slab < 4; ++slab) {
            __syncthreads();
            {
                int cin = tid >> 2, q = tid & 3;
                const float4* src = (const float4*)(xb + (size_t)cin * (HW * HW)
                                                    + xr * HW + slab * 64 + q * 16);
                float4 v0 = src[0], v1 = src[1], v2 = src[2], v3 = src[3];
                float* dp = stg + cin * 65 + q * 16;
                dp[0]=v0.x; dp[1]=v0.y; dp[2]=v0.z; dp[3]=v0.w;
                dp[4]=v1.x; dp[5]=v1.y; dp[6]=v1.z; dp[7]=v1.w;
                dp[8]=v2.x; dp[9]=v2.y; dp[10]=v2.z; dp[11]=v2.w;
                dp[12]=v3.x; dp[13]=v3.y; dp[14]=v3.z; dp[15]=v3.w;
            }
            __syncthreads();
            {
                int col = tid >> 2, q = tid & 3;
                int drow = slab * 64 + col + 16;
                unsigned hp[8], lp[8];
#pragma unroll
                for (int k = 0; k < 8; ++k) {
                    float v0 = stg[(q * 16 + 2 * k) * 65 + col];
                    float v1 = stg[(q * 16 + 2 * k + 1) * 65 + col];
                    __nv_bfloat16 h0 = __float2bfloat16(v0);
                    __nv_bfloat16 h1 = __float2bfloat16(v1);
                    __nv_bfloat16 l0 = __float2bfloat16(v0 - __bfloat162float(h0));
                    __nv_bfloat16 l1 = __float2bfloat16(v1 - __bfloat162float(h1));
                    hp[k] = (unsigned)*(unsigned short*)&h0
                          | ((unsigned)*(unsigned short*)&h1 << 16);
                    lp[k] = (unsigned)*(unsigned short*)&l0
                          | ((unsigned)*(unsigned short*)&l1 << 16);
                }
                unsigned ah = RCB + drow * 144 + q * 32;
                sts128(ah,      hp[0], hp[1], hp[2], hp[3]);
                sts128(ah + 16, hp[4], hp[5], hp[6], hp[7]);
                sts128(ah + RC_SPLIT,      lp[0], lp[1], lp[2], lp[3]);
                sts128(ah + RC_SPLIT + 16, lp[4], lp[5], lp[6], lp[7]);
            }
        }
        __syncthreads();

        // ---- taps of this kh ----
#pragma unroll 1
        for (int kw = 0; kw < K; ++kw) {
            const int off = D * kw - pad;
            __syncthreads();   // prior tap's ldmatrix reads of B done
            {
                // stage B tile [cout][cin] -> 144B-padded rows, both splits
                int n = tid >> 2, q = tid & 3;
                const uint4* sh = (const uint4*)(g_wS + (size_t)(TAPBASE + kh * K + kw) * 4096);
                const uint4* sl = (const uint4*)(g_wS + 671744 + (size_t)(TAPBASE + kh * K + kw) * 4096);
                int si = n * 8 + q * 2;
                uint4 h0 = __ldg(sh + si), h1 = __ldg(sh + si + 1);
                uint4 l0 = __ldg(sl + si), l1 = __ldg(sl + si + 1);
                unsigned db = BSB + n * 144 + q * 32;
                sts128(db,      h0.x, h0.y, h0.z, h0.w);
                sts128(db + 16, h1.x, h1.y, h1.z, h1.w);
                sts128(db + BS_SPLIT,      l0.x, l0.y, l0.z, l0.w);
                sts128(db + BS_SPLIT + 16, l1.x, l1.y, l1.z, l1.w);
            }
            __syncthreads();

#pragma unroll 1
            for (int kc = 0; kc < 4; ++kc) {
                unsigned aH[2][4], aL[2][4], bH[4][2], bL[4][2];
                // A fragments: rows are rc rows (stride 2 in rc space)
#pragma unroll
                for (int mt = 0; mt < 2; ++mt) {
                    int m = 32 * wm + 16 * mt + row16;
                    unsigned aaddr = RCB + (unsigned)(2 * m + off + 16) * 144
                                   + koffA + kc * 32;
                    ldsm4(aaddr, aH[mt]);
                    ldsm4(aaddr + RC_SPLIT, aL[mt]);
                }
                // B fragments: 2 ntile-pairs per x4
#pragma unroll
                for (int np = 0; np < 2; ++np) {
                    int n = 32 * wn + (2 * np + bnt) * 8 + brow;
                    unsigned baddr = BSB + (unsigned)n * 144 + bko + kc * 32;
                    unsigned t[4];
                    ldsm4(baddr, t);
                    bH[2*np][0]=t[0]; bH[2*np][1]=t[1];
                    bH[2*np+1][0]=t[2]; bH[2*np+1][1]=t[3];
                    ldsm4(baddr + BS_SPLIT, t);
                    bL[2*np][0]=t[0]; bL[2*np][1]=t[1];
                    bL[2*np+1][0]=t[2]; bL[2*np+1][1]=t[3];
                }
                // 3 split segments
#pragma unroll
                for (int mt = 0; mt < 2; ++mt)
#pragma unroll
                    for (int nt = 0; nt < 4; ++nt)
                        mma16816(d[mt][nt], aH[mt], bH[nt]);
#pragma unroll
                for (int mt = 0; mt < 2; ++mt)
#pragma unroll
                    for (int nt = 0; nt < 4; ++nt)
                        mma16816(d[mt][nt], aL[mt], bH[nt]);
#pragma unroll
                for (int mt = 0; mt < 2; ++mt)
#pragma unroll
                    for (int nt = 0; nt < 4; ++nt)
                        mma16816(d[mt][nt], aH[mt], bL[nt]);
            }
        }
    }

    // ---- epilogue: BN fold + exact GELU + gate weight ----
    const float wt = g_selwt[z];
    const int b = z >> 1, s = z & 1;
#pragma unroll
    for (int mt = 0; mt < 2; ++mt)
#pragma unroll
        for (int nt = 0; nt < 4; ++nt)
#pragma unroll
            for (int c = 0; c < 4; ++c) {
                int ow = 32 * wm + 16 * mt + (lane >> 2) + ((c >= 2) ? 8 : 0);
                int cout = 32 * wn + 8 * nt + (lane & 3) * 2 + (c & 1);
                float v = d[mt][nt][c];
                float y = v * g_bnA[E * 64 + cout] + g_bnB[E * 64 + cout];
                y = 0.5f * y * (1.f + erff(y * 0.70710678118654752f));
                out[((size_t)(b * 128 + s * 64 + cout)) * (HO * HO)
                    + oh * HO + ow] = y * wt;
            }
}

__global__ void __launch_bounds__(256, 2)
conv_all_kernel(const float* __restrict__ x, float* __restrict__ out) {
    extern __shared__ char smem[];
    unsigned sbase = smem_u32(smem);
    const int z = g_sched[blockIdx.y];          // heavy-first schedule
    const int e = g_selidx[z];
    const float* xb = x + (size_t)(z >> 1) * CIN * HW * HW;
    if (e == 0)      conv_body<0, 3, 1, 0 >(xb, out, z, smem, sbase);
    else if (e == 1) conv_body<1, 5, 2, 9 >(xb, out, z, smem, sbase);
    else if (e == 2) conv_body<2, 7, 3, 34>(xb, out, z, smem, sbase);
    else             conv_body<3, 9, 4, 83>(xb, out, z, smem, sbase);
}

// ---------------- launch: exactly 4 launches, conv is #4 (ncu capture slot) -----
extern "C" void kernel_launch(void* const* d_in, const int* in_sizes, int n_in,
                              void* d_out, int out_size) {
    (void)in_sizes; (void)n_in; (void)out_size;
    const float* x   = (const float*)d_in[0];
    const float* w0  = (const float*)d_in[1];
    const float* b0  = (const float*)d_in[2];
    const float* w1  = (const float*)d_in[3];
    const float* b1  = (const float*)d_in[4];
    const float* w2  = (const float*)d_in[5];
    const float* b2  = (const float*)d_in[6];
    const float* w3  = (const float*)d_in[7];
    const float* b3  = (const float*)d_in[8];
    const float* bns = (const float*)d_in[9];
    const float* bnb = (const float*)d_in[10];
    const float* bnm = (const float*)d_in[11];
    const float* bnv = (const float*)d_in[12];
    const float* gw  = (const float*)d_in[13];
    const float* gb  = (const float*)d_in[14];
    float* out = (float*)d_out;

    static int s_attr_set = 0;
    if (!s_attr_set) {
        cudaFuncSetAttribute(conv_all_kernel,
                             cudaFuncAttributeMaxDynamicSharedMemorySize,
                             CONV_SMEM);
        s_attr_set = 1;
    }

    pool_kernel<<<NB * CIN, 256>>>(x);                                   // #1
    wsplit_kernel<<<(164 * 4096 + 255) / 256, 256>>>(w0, w1, w2, w3);    // #2
    gatebn_kernel<<<1, 256>>>(gw, gb, bns, bnb, bnm, bnv,
                              b0, b1, b2, b3);                           // #3
    dim3 grid(128, NB * 2);   // oh x (b,slot heavy-first)
    conv_all_kernel<<<grid, 256, CONV_SMEM>>>(x, out);                   // #4
}

// round 15
// speedup vs baseline: 1.8346x; 1.0576x over previous
#include <cuda_runtime.h>
#include <cuda_bf16.h>
#include <math.h>

#define CIN 64
#define HW  256
#define HO  128
#define NB  16

// ---------------- device scratch (no allocations allowed) ----------------
__device__ float g_pooled[NB * CIN];
__device__ int   g_selidx[NB * 2];
__device__ float g_selwt [NB * 2];
__device__ int   g_sched [NB * 2];
__device__ float g_bnA[4 * 64];
__device__ float g_bnB[4 * 64];
// split weights: [split(2)][tapflat(164)][cout(64)][cin(64)] bf16
// tap offsets: E0:0(9), E1:9(25), E2:34(49), E3:83(81) -> 164 taps
__device__ __align__(16) __nv_bfloat16 g_wS[2 * 164 * 4096];

// ---------------- launch #1: global average pool ----------------
__global__ void pool_kernel(const float* __restrict__ x) {
    __shared__ float red[256];
    int tid = threadIdx.x;
    const float4* xp = (const float4*)(x + (size_t)blockIdx.x * (HW * HW));
    float s = 0.f;
    for (int i = tid; i < HW * HW / 4; i += 256) {
        float4 v = xp[i];
        s += (v.x + v.y) + (v.z + v.w);
    }
    red[tid] = s;
    __syncthreads();
    for (int off = 128; off > 0; off >>= 1) {
        if (tid < off) red[tid] += red[tid + off];
        __syncthreads();
    }
    if (tid == 0) g_pooled[blockIdx.x] = red[0] * (1.f / (HW * HW));
}

// ---------------- launch #2: weight split to bf16 hi/lo ----------------
__global__ void wsplit_kernel(const float* __restrict__ w0, const float* __restrict__ w1,
                              const float* __restrict__ w2, const float* __restrict__ w3) {
    int i = blockIdx.x * 256 + threadIdx.x;
    if (i >= 164 * 4096) return;
    int cin  = i & 63;
    int cout = (i >> 6) & 63;
    int tapf = i >> 12;
    const float* w; int KK, kidx;
    if (tapf < 9)       { w = w0; KK = 9;  kidx = tapf; }
    else if (tapf < 34) { w = w1; KK = 25; kidx = tapf - 9; }
    else if (tapf < 83) { w = w2; KK = 49; kidx = tapf - 34; }
    else                { w = w3; KK = 81; kidx = tapf - 83; }
    float v = w[(cout * 64 + cin) * KK + kidx];
    __nv_bfloat16 hi = __float2bfloat16(v);
    __nv_bfloat16 lo = __float2bfloat16(v - __bfloat162float(hi));
    g_wS[i] = hi;
    g_wS[671744 + i] = lo;
}

// ---------------- launch #3: gate + bn fold + schedule ----------------
__global__ void gatebn_kernel(const float* __restrict__ gw, const float* __restrict__ gb,
                              const float* __restrict__ sc, const float* __restrict__ bi,
                              const float* __restrict__ me, const float* __restrict__ va,
                              const float* __restrict__ b0, const float* __restrict__ b1,
                              const float* __restrict__ b2, const float* __restrict__ b3) {
    __shared__ int s_idx[NB * 2];
    int t = threadIdx.x;
    {
        const float* bb = (t < 64) ? b0 : (t < 128) ? b1 : (t < 192) ? b2 : b3;
        float inv = sc[t] * rsqrtf(va[t] + 1e-5f);
        g_bnA[t] = inv;
        g_bnB[t] = bb[t & 63] * inv + bi[t] - me[t] * inv;
    }
    if (t < NB) {
        int b = t;
        float lg[4];
        for (int e = 0; e < 4; ++e) {
            float s = gb[e];
            for (int c = 0; c < CIN; ++c) s += g_pooled[b * CIN + c] * gw[e * CIN + c];
            lg[e] = s;
        }
        float m = fmaxf(fmaxf(lg[0], lg[1]), fmaxf(lg[2], lg[3]));
        float p[4]; float Z = 0.f;
        for (int e = 0; e < 4; ++e) { p[e] = expf(lg[e] - m); Z += p[e]; }
        for (int e = 0; e < 4; ++e) p[e] /= Z;
        int i0 = 0;
        for (int e = 1; e < 4; ++e) if (p[e] > p[i0]) i0 = e;
        int i1 = -1;
        for (int e = 0; e < 4; ++e) {
            if (e == i0) continue;
            if (i1 < 0 || p[e] > p[i1]) i1 = e;
        }
        float den = p[i0] + p[i1] + 1e-8f;
        g_selidx[b * 2 + 0] = i0; g_selwt[b * 2 + 0] = p[i0] / den;
        g_selidx[b * 2 + 1] = i1; g_selwt[b * 2 + 1] = p[i1] / den;
        s_idx[b * 2 + 0] = i0;
        s_idx[b * 2 + 1] = i1;
    }
    __syncthreads();
    if (t == 0) {
        int n = 0;
        for (int e = 3; e >= 0; --e)
            for (int z = 0; z < NB * 2; ++z)
                if (s_idx[z] == e) g_sched[n++] = z;
    }
}

// ---------------- mma.sync helpers (sm_80+ ISA, valid on plain sm_100) ----------
__device__ __forceinline__ unsigned smem_u32(const void* p) {
    return (unsigned)__cvta_generic_to_shared(p);
}
__device__ __forceinline__ void sts128(unsigned a, unsigned r0, unsigned r1,
                                       unsigned r2, unsigned r3) {
    asm volatile("st.shared.v4.b32 [%0], {%1,%2,%3,%4};"
                 :: "r"(a), "r"(r0), "r"(r1), "r"(r2), "r"(r3) : "memory");
}
__device__ __forceinline__ void ldsm4(unsigned a, unsigned* r) {
    asm volatile("ldmatrix.sync.aligned.m8n8.x4.shared.b16 {%0,%1,%2,%3}, [%4];"
                 : "=r"(r[0]), "=r"(r[1]), "=r"(r[2]), "=r"(r[3]) : "r"(a));
}
__device__ __forceinline__ void mma16816(float* d, const unsigned* a, const unsigned* b) {
    asm volatile(
        "mma.sync.aligned.m16n8k16.row.col.f32.bf16.bf16.f32 "
        "{%0,%1,%2,%3}, {%4,%5,%6,%7}, {%8,%9}, {%0,%1,%2,%3};"
        : "+f"(d[0]), "+f"(d[1]), "+f"(d[2]), "+f"(d[3])
        : "r"(a[0]), "r"(a[1]), "r"(a[2]), "r"(a[3]), "r"(b[0]), "r"(b[1]));
}

// smem layout (dynamic, 144B rows for conflict-free LDSM):
//   rc: PARITY-SPLIT row cache [parity(2)][split(2)][160 rows][144B] = 92160
//       even array row i = pixel 2i, odd array row i = pixel 2i+1 (i = phys-16);
//       rows 0..15 and 144..159 are permanent zero halos (vertical OOB too).
//       A ldsm rows now stride 144B (was 288B) -> conflict-free (was 2-way).
//   BS: per-tap B tile [split2][64][144B] = 18432, unioned with
//   stg: 64x65 f32 transpose staging (16640)
#define RC_PAR   46080
#define RC_SPLIT 23040
#define SM_BS    92160
#define BS_SPLIT 9216
#define CONV_SMEM 110592

// ---------------- launch #4: mma.sync bf16-split implicit conv ----------------
// CTA = (z, oh). D[128 ow x 64 cout] += sum_taps A[128 x 64cin] . W[64cout x 64cin]^T
// 3 split segments (hi.hi + lo.hi + hi.lo), fp32 register accumulators.
// 8 warps = 4 (M strips of 32) x 2 (N halves of 32); per warp 2x4 m16n8 tiles.
template <int E, int K, int D, int TAPBASE>
__device__ void conv_body(const float* __restrict__ xb, float* __restrict__ out,
                          int z, char* smem, unsigned sbase) {
    const int tid = threadIdx.x, lane = tid & 31, wid = tid >> 5;
    const int wm = wid >> 1, wn = wid & 1;
    const int oh = blockIdx.x;
    const int pad = D * (K - 1) / 2;
    const unsigned RCB = sbase, BSB = sbase + SM_BS;
    float* stg = (float*)(smem + SM_BS);

    // zero halo rows (phys 0..15 and 144..159) in all 4 parity/split arrays
    for (int i = tid; i < 1152; i += 256) {        // 4 arrays * 32 rows * 9 chunks
        int c = i % 9;
        int row = i / 9;                            // 0..127
        int arr = row >> 5;                         // parity*2+split
        int r = row & 31;
        int phys = (r < 16) ? r : (128 + r);        // 0..15 or 144..159
        sts128(RCB + arr * RC_SPLIT + phys * 144 + c * 16, 0, 0, 0, 0);
    }

    float d[2][4][4];
#pragma unroll
    for (int mt = 0; mt < 2; ++mt)
#pragma unroll
        for (int nt = 0; nt < 4; ++nt)
#pragma unroll
            for (int c = 0; c < 4; ++c) d[mt][nt][c] = 0.f;

    // ldmatrix lane mappings
    const int row16 = lane & 15;
    const int koffA = (lane >> 4) * 16;
    const int bsel = lane >> 3, brow = lane & 7;
    const int bnt = bsel >> 1;
    const int bko = (bsel & 1) * 16;

#pragma unroll 1
    for (int kh = 0; kh < K; ++kh) {
        int xr = 2 * oh - pad + D * kh;
        if ((unsigned)xr >= (unsigned)HW) continue;   // vertical OOB => zero tap row

        // ---- rebuild row cache: transpose + bf16 split, parity-separated ----
#pragma unroll 1
        for (int slab = 0; slab < 4; ++slab) {
            __syncthreads();
            {
                int cin = tid >> 2, q = tid & 3;
                const float4* src = (const float4*)(xb + (size_t)cin * (HW * HW)
                                                    + xr * HW + slab * 64 + q * 16);
                float4 v0 = src[0], v1 = src[1], v2 = src[2], v3 = src[3];
                float* dp = stg + cin * 65 + q * 16;
                dp[0]=v0.x; dp[1]=v0.y; dp[2]=v0.z; dp[3]=v0.w;
                dp[4]=v1.x; dp[5]=v1.y; dp[6]=v1.z; dp[7]=v1.w;
                dp[8]=v2.x; dp[9]=v2.y; dp[10]=v2.z; dp[11]=v2.w;
                dp[12]=v3.x; dp[13]=v3.y; dp[14]=v3.z; dp[15]=v3.w;
            }
            __syncthreads();
            {
                int col = tid >> 2, q = tid & 3;   // col = pixel within slab
                int p = slab * 64 + col;
                int pr = p & 1;
                int phys = (p >> 1) + 16;
                unsigned hp[8], lp[8];
#pragma unroll
                for (int k = 0; k < 8; ++k) {
                    float v0 = stg[(q * 16 + 2 * k) * 65 + col];
                    float v1 = stg[(q * 16 + 2 * k + 1) * 65 + col];
                    __nv_bfloat16 h0 = __float2bfloat16(v0);
                    __nv_bfloat16 h1 = __float2bfloat16(v1);
                    __nv_bfloat16 l0 = __float2bfloat16(v0 - __bfloat162float(h0));
                    __nv_bfloat16 l1 = __float2bfloat16(v1 - __bfloat162float(h1));
                    hp[k] = (unsigned)*(unsigned short*)&h0
                          | ((unsigned)*(unsigned short*)&h1 << 16);
                    lp[k] = (unsigned)*(unsigned short*)&l0
                          | ((unsigned)*(unsigned short*)&l1 << 16);
                }
                unsigned ah = RCB + pr * RC_PAR + phys * 144 + q * 32;
                sts128(ah,      hp[0], hp[1], hp[2], hp[3]);
                sts128(ah + 16, hp[4], hp[5], hp[6], hp[7]);
                sts128(ah + RC_SPLIT,      lp[0], lp[1], lp[2], lp[3]);
                sts128(ah + RC_SPLIT + 16, lp[4], lp[5], lp[6], lp[7]);
            }
        }
        __syncthreads();

        // ---- taps of this kh ----
#pragma unroll 1
        for (int kw = 0; kw < K; ++kw) {
            const int off = D * kw - pad;
            const int pr = off & 1;
            const int ibase = ((off - pr) >> 1) + 16;   // row base in parity array
            const unsigned ABase = RCB + pr * RC_PAR;
            __syncthreads();   // prior tap's ldmatrix reads of B done
            {
                // stage B tile [cout][cin] -> 144B rows, both splits
                int n = tid >> 2, q = tid & 3;
                const uint4* sh = (const uint4*)(g_wS + (size_t)(TAPBASE + kh * K + kw) * 4096);
                const uint4* sl = (const uint4*)(g_wS + 671744 + (size_t)(TAPBASE + kh * K + kw) * 4096);
                int si = n * 8 + q * 2;
                uint4 h0 = __ldg(sh + si), h1 = __ldg(sh + si + 1);
                uint4 l0 = __ldg(sl + si), l1 = __ldg(sl + si + 1);
                unsigned db = BSB + n * 144 + q * 32;
                sts128(db,      h0.x, h0.y, h0.z, h0.w);
                sts128(db + 16, h1.x, h1.y, h1.z, h1.w);
                sts128(db + BS_SPLIT,      l0.x, l0.y, l0.z, l0.w);
                sts128(db + BS_SPLIT + 16, l1.x, l1.y, l1.z, l1.w);
            }
            __syncthreads();

#pragma unroll 1
            for (int kc = 0; kc < 4; ++kc) {
                unsigned aH[2][4], aL[2][4], bH[4][2], bL[4][2];
                // A fragments: consecutive m -> consecutive 144B rows (conflict-free)
#pragma unroll
                for (int mt = 0; mt < 2; ++mt) {
                    int m = 32 * wm + 16 * mt + row16;
                    unsigned aaddr = ABase + (unsigned)(m + ibase) * 144
                                   + koffA + kc * 32;
                    ldsm4(aaddr, aH[mt]);
                    ldsm4(aaddr + RC_SPLIT, aL[mt]);
                }
                // B fragments: 2 ntile-pairs per x4
#pragma unroll
                for (int np = 0; np < 2; ++np) {
                    int n = 32 * wn + (2 * np + bnt) * 8 + brow;
                    unsigned baddr = BSB + (unsigned)n * 144 + bko + kc * 32;
                    unsigned t[4];
                    ldsm4(baddr, t);
                    bH[2*np][0]=t[0]; bH[2*np][1]=t[1];
                    bH[2*np+1][0]=t[2]; bH[2*np+1][1]=t[3];
                    ldsm4(baddr + BS_SPLIT, t);
                    bL[2*np][0]=t[0]; bL[2*np][1]=t[1];
                    bL[2*np+1][0]=t[2]; bL[2*np+1][1]=t[3];
                }
                // 3 split segments
#pragma unroll
                for (int mt = 0; mt < 2; ++mt)
#pragma unroll
                    for (int nt = 0; nt < 4; ++nt)
                        mma16816(d[mt][nt], aH[mt], bH[nt]);
#pragma unroll
                for (int mt = 0; mt < 2; ++mt)
#pragma unroll
                    for (int nt = 0; nt < 4; ++nt)
                        mma16816(d[mt][nt], aL[mt], bH[nt]);
#pragma unroll
                for (int mt = 0; mt < 2; ++mt)
#pragma unroll
                    for (int nt = 0; nt < 4; ++nt)
                        mma16816(d[mt][nt], aH[mt], bL[nt]);
            }
        }
    }

    // ---- epilogue: BN fold + exact GELU + gate weight ----
    const float wt = g_selwt[z];
    const int b = z >> 1, s = z & 1;
#pragma unroll
    for (int mt = 0; mt < 2; ++mt)
#pragma unroll
        for (int nt = 0; nt < 4; ++nt)
#pragma unroll
            for (int c = 0; c < 4; ++c) {
                int ow = 32 * wm + 16 * mt + (lane >> 2) + ((c >= 2) ? 8 : 0);
                int cout = 32 * wn + 8 * nt + (lane & 3) * 2 + (c & 1);
                float v = d[mt][nt][c];
                float y = v * g_bnA[E * 64 + cout] + g_bnB[E * 64 + cout];
                y = 0.5f * y * (1.f + erff(y * 0.70710678118654752f));
                out[((size_t)(b * 128 + s * 64 + cout)) * (HO * HO)
                    + oh * HO + ow] = y * wt;
            }
}

__global__ void __launch_bounds__(256, 2)
conv_all_kernel(const float* __restrict__ x, float* __restrict__ out) {
    extern __shared__ char smem[];
    unsigned sbase = smem_u32(smem);
    const int z = g_sched[blockIdx.y];          // heavy-first schedule
    const int e = g_selidx[z];
    const float* xb = x + (size_t)(z >> 1) * CIN * HW * HW;
    if (e == 0)      conv_body<0, 3, 1, 0 >(xb, out, z, smem, sbase);
    else if (e == 1) conv_body<1, 5, 2, 9 >(xb, out, z, smem, sbase);
    else if (e == 2) conv_body<2, 7, 3, 34>(xb, out, z, smem, sbase);
    else             conv_body<3, 9, 4, 83>(xb, out, z, smem, sbase);
}

// ---------------- launch: exactly 4 launches, conv is #4 (ncu capture slot) -----
extern "C" void kernel_launch(void* const* d_in, const int* in_sizes, int n_in,
                              void* d_out, int out_size) {
    (void)in_sizes; (void)n_in; (void)out_size;
    const float* x   = (const float*)d_in[0];
    const float* w0  = (const float*)d_in[1];
    const float* b0  = (const float*)d_in[2];
    const float* w1  = (const float*)d_in[3];
    const float* b1  = (const float*)d_in[4];
    const float* w2  = (const float*)d_in[5];
    const float* b2  = (const float*)d_in[6];
    const float* w3  = (const float*)d_in[7];
    const float* b3  = (const float*)d_in[8];
    const float* bns = (const float*)d_in[9];
    const float* bnb = (const float*)d_in[10];
    const float* bnm = (const float*)d_in[11];
    const float* bnv = (const float*)d_in[12];
    const float* gw  = (const float*)d_in[13];
    const float* gb  = (const float*)d_in[14];
    float* out = (float*)d_out;

    static int s_attr_set = 0;
    if (!s_attr_set) {
        cudaFuncSetAttribute(conv_all_kernel,
                             cudaFuncAttributeMaxDynamicSharedMemorySize,
                             CONV_SMEM);
        s_attr_set = 1;
    }

    pool_kernel<<<NB * CIN, 256>>>(x);                                   // #1
    wsplit_kernel<<<(164 * 4096 + 255) / 256, 256>>>(w0, w1, w2, w3);    // #2
    gatebn_kernel<<<1, 256>>>(gw, gb, bns, bnb, bnm, bnv,
                              b0, b1, b2, b3);                           // #3
    dim3 grid(128, NB * 2);   // oh x (b,slot heavy-first)
    conv_all_kernel<<<grid, 256, CONV_SMEM>>>(x, out);                   // #4
}

// round 16
// speedup vs baseline: 2.3099x; 1.2591x over previous
#include <cuda_runtime.h>
#include <cuda_fp16.h>
#include <math.h>

#define CIN 64
#define HW  256
#define HO  128
#define NB  16

// ---------------- device scratch (no allocations allowed) ----------------
__device__ float g_pooled[NB * CIN];
__device__ int   g_selidx[NB * 2];
__device__ float g_selwt [NB * 2];
__device__ int   g_sched [NB * 2];
__device__ float g_bnA[4 * 64];
__device__ float g_bnB[4 * 64];
// split weights: [split(2)][tapflat(164)][cout(64)][cin(64)] fp16
// tap offsets: E0:0(9), E1:9(25), E2:34(49), E3:83(81) -> 164 taps
__device__ __align__(16) __half g_wS[2 * 164 * 4096];

// ---------------- launch #1: global average pool ----------------
__global__ void pool_kernel(const float* __restrict__ x) {
    __shared__ float red[256];
    int tid = threadIdx.x;
    const float4* xp = (const float4*)(x + (size_t)blockIdx.x * (HW * HW));
    float s = 0.f;
    for (int i = tid; i < HW * HW / 4; i += 256) {
        float4 v = xp[i];
        s += (v.x + v.y) + (v.z + v.w);
    }
    red[tid] = s;
    __syncthreads();
    for (int off = 128; off > 0; off >>= 1) {
        if (tid < off) red[tid] += red[tid + off];
        __syncthreads();
    }
    if (tid == 0) g_pooled[blockIdx.x] = red[0] * (1.f / (HW * HW));
}

// ---------------- launch #2: weight split to fp16 hi/lo ----------------
__global__ void wsplit_kernel(const float* __restrict__ w0, const float* __restrict__ w1,
                              const float* __restrict__ w2, const float* __restrict__ w3) {
    int i = blockIdx.x * 256 + threadIdx.x;
    if (i >= 164 * 4096) return;
    int cin  = i & 63;
    int cout = (i >> 6) & 63;
    int tapf = i >> 12;
    const float* w; int KK, kidx;
    if (tapf < 9)       { w = w0; KK = 9;  kidx = tapf; }
    else if (tapf < 34) { w = w1; KK = 25; kidx = tapf - 9; }
    else if (tapf < 83) { w = w2; KK = 49; kidx = tapf - 34; }
    else                { w = w3; KK = 81; kidx = tapf - 83; }
    float v = w[(cout * 64 + cin) * KK + kidx];
    __half hi = __float2half_rn(v);
    __half lo = __float2half_rn(v - __half2float(hi));
    g_wS[i] = hi;
    g_wS[671744 + i] = lo;
}

// ---------------- launch #3: gate + bn fold + schedule ----------------
__global__ void gatebn_kernel(const float* __restrict__ gw, const float* __restrict__ gb,
                              const float* __restrict__ sc, const float* __restrict__ bi,
                              const float* __restrict__ me, const float* __restrict__ va,
                              const float* __restrict__ b0, const float* __restrict__ b1,
                              const float* __restrict__ b2, const float* __restrict__ b3) {
    __shared__ int s_idx[NB * 2];
    int t = threadIdx.x;
    {
        const float* bb = (t < 64) ? b0 : (t < 128) ? b1 : (t < 192) ? b2 : b3;
        float inv = sc[t] * rsqrtf(va[t] + 1e-5f);
        g_bnA[t] = inv;
        g_bnB[t] = bb[t & 63] * inv + bi[t] - me[t] * inv;
    }
    if (t < NB) {
        int b = t;
        float lg[4];
        for (int e = 0; e < 4; ++e) {
            float s = gb[e];
            for (int c = 0; c < CIN; ++c) s += g_pooled[b * CIN + c] * gw[e * CIN + c];
            lg[e] = s;
        }
        float m = fmaxf(fmaxf(lg[0], lg[1]), fmaxf(lg[2], lg[3]));
        float p[4]; float Z = 0.f;
        for (int e = 0; e < 4; ++e) { p[e] = expf(lg[e] - m); Z += p[e]; }
        for (int e = 0; e < 4; ++e) p[e] /= Z;
        int i0 = 0;
        for (int e = 1; e < 4; ++e) if (p[e] > p[i0]) i0 = e;
        int i1 = -1;
        for (int e = 0; e < 4; ++e) {
            if (e == i0) continue;
            if (i1 < 0 || p[e] > p[i1]) i1 = e;
        }
        float den = p[i0] + p[i1] + 1e-8f;
        g_selidx[b * 2 + 0] = i0; g_selwt[b * 2 + 0] = p[i0] / den;
        g_selidx[b * 2 + 1] = i1; g_selwt[b * 2 + 1] = p[i1] / den;
        s_idx[b * 2 + 0] = i0;
        s_idx[b * 2 + 1] = i1;
    }
    __syncthreads();
    if (t == 0) {
        int n = 0;
        for (int e = 3; e >= 0; --e)
            for (int z = 0; z < NB * 2; ++z)
                if (s_idx[z] == e) g_sched[n++] = z;
    }
}

// ---------------- mma.sync helpers (sm_80+ ISA, valid on plain sm_100) ----------
__device__ __forceinline__ unsigned smem_u32(const void* p) {
    return (unsigned)__cvta_generic_to_shared(p);
}
__device__ __forceinline__ void sts128(unsigned a, unsigned r0, unsigned r1,
                                       unsigned r2, unsigned r3) {
    asm volatile("st.shared.v4.b32 [%0], {%1,%2,%3,%4};"
                 :: "r"(a), "r"(r0), "r"(r1), "r"(r2), "r"(r3) : "memory");
}
__device__ __forceinline__ void ldsm4(unsigned a, unsigned* r) {
    asm volatile("ldmatrix.sync.aligned.m8n8.x4.shared.b16 {%0,%1,%2,%3}, [%4];"
                 : "=r"(r[0]), "=r"(r[1]), "=r"(r[2]), "=r"(r[3]) : "r"(a));
}
__device__ __forceinline__ void mma16816(float* d, const unsigned* a, const unsigned* b) {
    asm volatile(
        "mma.sync.aligned.m16n8k16.row.col.f32.f16.f16.f32 "
        "{%0,%1,%2,%3}, {%4,%5,%6,%7}, {%8,%9}, {%0,%1,%2,%3};"
        : "+f"(d[0]), "+f"(d[1]), "+f"(d[2]), "+f"(d[3])
        : "r"(a[0]), "r"(a[1]), "r"(a[2]), "r"(a[3]), "r"(b[0]), "r"(b[1]));
}

// smem layout (dynamic, 144B rows for conflict-free LDSM):
//   rc: parity-split x cache [parity(2)][144 rows][144B] = 41472, fp16 (hi only).
//       row i of parity array = pixel 2i+pr (i = phys-8); rows 0..7 and
//       136..143 are permanent zero halos (pad<=16 -> parity offset <=8).
//   BS: DOUBLE-BUFFERED per-tap B tile [buf2][split2][64][144B] = 36864,
//       unioned with the 64x65 f32 transpose staging (16640).
#define RC_PAR   20736
#define SM_BS    41472
#define BS_BUF   18432
#define BS_SPLIT 9216
#define CONV_SMEM 78336

__device__ __forceinline__ void stage_B(unsigned dst, int tapidx, int tid) {
    int n = tid >> 2, q = tid & 3;
    const uint4* sh = (const uint4*)(g_wS + (size_t)tapidx * 4096);
    const uint4* sl = (const uint4*)(g_wS + 671744 + (size_t)tapidx * 4096);
    int si = n * 8 + q * 2;
    uint4 h0 = __ldg(sh + si), h1 = __ldg(sh + si + 1);
    uint4 l0 = __ldg(sl + si), l1 = __ldg(sl + si + 1);
    unsigned db = dst + n * 144 + q * 32;
    sts128(db,      h0.x, h0.y, h0.z, h0.w);
    sts128(db + 16, h1.x, h1.y, h1.z, h1.w);
    sts128(db + BS_SPLIT,      l0.x, l0.y, l0.z, l0.w);
    sts128(db + BS_SPLIT + 16, l1.x, l1.y, l1.z, l1.w);
}

// ---------------- launch #4: mma.sync fp16 2-segment implicit conv -------------
// CTA = (z, oh). D[128 ow x 64 cout] += sum_taps A[128 x 64cin] . W[64cout x 64cin]^T
// x quantized once to fp16 (error ~2^-12, random sign); W split exactly into
// fp16 hi+lo -> 2 MMA segments: xh.wh + xh.wl. fp32 accumulators.
// 8 warps = 4 (M strips of 32) x 2 (N halves of 32); per warp 2x4 m16n8 tiles.
template <int E, int K, int D, int TAPBASE>
__device__ void conv_body(const float* __restrict__ xb, float* __restrict__ out,
                          int z, char* smem, unsigned sbase) {
    const int tid = threadIdx.x, lane = tid & 31, wid = tid >> 5;
    const int wm = wid >> 1, wn = wid & 1;
    const int oh = blockIdx.x;
    const int pad = D * (K - 1) / 2;
    const unsigned RCB = sbase, BSB = sbase + SM_BS;
    float* stg = (float*)(smem + SM_BS);

    // zero halo rows (phys 0..7 and 136..143) in both parity arrays
    for (int i = tid; i < 288; i += 256) {        // 2 arrays * 16 rows * 9 chunks
        int c = i % 9;
        int row = i / 9;                           // 0..31
        int arr = row >> 4;                        // parity
        int r = row & 15;
        int phys = (r < 8) ? r : (128 + r);        // 0..7 or 136..143
        sts128(RCB + arr * RC_PAR + phys * 144 + c * 16, 0, 0, 0, 0);
    }

    float d[2][4][4];
#pragma unroll
    for (int mt = 0; mt < 2; ++mt)
#pragma unroll
        for (int nt = 0; nt < 4; ++nt)
#pragma unroll
            for (int c = 0; c < 4; ++c) d[mt][nt][c] = 0.f;

    // ldmatrix lane mappings
    const int row16 = lane & 15;
    const int koffA = (lane >> 4) * 16;
    const int bsel = lane >> 3, brow = lane & 7;
    const int bnt = bsel >> 1;
    const int bko = (bsel & 1) * 16;

#pragma unroll 1
    for (int kh = 0; kh < K; ++kh) {
        int xr = 2 * oh - pad + D * kh;
        if ((unsigned)xr >= (unsigned)HW) continue;   // vertical OOB => zero tap row

        // ---- rebuild row cache: transpose + fp16 quantize, parity-separated ----
#pragma unroll 1
        for (int slab = 0; slab < 4; ++slab) {
            __syncthreads();
            {
                int cin = tid >> 2, q = tid & 3;
                const float4* src = (const float4*)(xb + (size_t)cin * (HW * HW)
                                                    + xr * HW + slab * 64 + q * 16);
                float4 v0 = src[0], v1 = src[1], v2 = src[2], v3 = src[3];
                float* dp = stg + cin * 65 + q * 16;
                dp[0]=v0.x; dp[1]=v0.y; dp[2]=v0.z; dp[3]=v0.w;
                dp[4]=v1.x; dp[5]=v1.y; dp[6]=v1.z; dp[7]=v1.w;
                dp[8]=v2.x; dp[9]=v2.y; dp[10]=v2.z; dp[11]=v2.w;
                dp[12]=v3.x; dp[13]=v3.y; dp[14]=v3.z; dp[15]=v3.w;
            }
            __syncthreads();
            {
                int col = tid >> 2, q = tid & 3;   // col = pixel within slab
                int p = slab * 64 + col;
                int pr = p & 1;
                int phys = (p >> 1) + 8;
                unsigned hp[8];
#pragma unroll
                for (int k = 0; k < 8; ++k) {
                    __half h0 = __float2half_rn(stg[(q * 16 + 2 * k) * 65 + col]);
                    __half h1 = __float2half_rn(stg[(q * 16 + 2 * k + 1) * 65 + col]);
                    hp[k] = (unsigned)*(unsigned short*)&h0
                          | ((unsigned)*(unsigned short*)&h1 << 16);
                }
                unsigned ah = RCB + pr * RC_PAR + phys * 144 + q * 32;
                sts128(ah,      hp[0], hp[1], hp[2], hp[3]);
                sts128(ah + 16, hp[4], hp[5], hp[6], hp[7]);
            }
        }
        __syncthreads();

        // ---- taps of this kh, B tile double-buffered (1 barrier per tap) ----
        stage_B(BSB, TAPBASE + kh * K, tid);
        __syncthreads();
#pragma unroll 1
        for (int kw = 0; kw < K; ++kw) {
            if (kw + 1 < K)
                stage_B(BSB + ((kw + 1) & 1) * BS_BUF, TAPBASE + kh * K + kw + 1, tid);

            const unsigned BUF = BSB + (kw & 1) * BS_BUF;
            const int off = D * kw - pad;
            const int pr = off & 1;
            const int ibase = ((off - pr) >> 1) + 8;
            const unsigned ABase = RCB + pr * RC_PAR;

#pragma unroll 1
            for (int kc = 0; kc < 4; ++kc) {
                unsigned aH[2][4], bH[4][2], bL[4][2];
#pragma unroll
                for (int mt = 0; mt < 2; ++mt) {
                    int m = 32 * wm + 16 * mt + row16;
                    ldsm4(ABase + (unsigned)(m + ibase) * 144 + koffA + kc * 32, aH[mt]);
                }
#pragma unroll
                for (int np = 0; np < 2; ++np) {
                    int n = 32 * wn + (2 * np + bnt) * 8 + brow;
                    unsigned baddr = BUF + (unsigned)n * 144 + bko + kc * 32;
                    unsigned t[4];
                    ldsm4(baddr, t);
                    bH[2*np][0]=t[0]; bH[2*np][1]=t[1];
                    bH[2*np+1][0]=t[2]; bH[2*np+1][1]=t[3];
                    ldsm4(baddr + BS_SPLIT, t);
                    bL[2*np][0]=t[0]; bL[2*np][1]=t[1];
                    bL[2*np+1][0]=t[2]; bL[2*np+1][1]=t[3];
                }
#pragma unroll
                for (int mt = 0; mt < 2; ++mt)
#pragma unroll
                    for (int nt = 0; nt < 4; ++nt)
                        mma16816(d[mt][nt], aH[mt], bH[nt]);
#pragma unroll
                for (int mt = 0; mt < 2; ++mt)
#pragma unroll
                    for (int nt = 0; nt < 4; ++nt)
                        mma16816(d[mt][nt], aH[mt], bL[nt]);
            }
            __syncthreads();   // next tap's staging visible; this tap's reads done
        }
    }

    // ---- epilogue: BN fold + exact GELU + gate weight ----
    const float wt = g_selwt[z];
    const int b = z >> 1, s = z & 1;
#pragma unroll
    for (int mt = 0; mt < 2; ++mt)
#pragma unroll
        for (int nt = 0; nt < 4; ++nt)
#pragma unroll
            for (int c = 0; c < 4; ++c) {
                int ow = 32 * wm + 16 * mt + (lane >> 2) + ((c >= 2) ? 8 : 0);
                int cout = 32 * wn + 8 * nt + (lane & 3) * 2 + (c & 1);
                float v = d[mt][nt][c];
                float y = v * g_bnA[E * 64 + cout] + g_bnB[E * 64 + cout];
                y = 0.5f * y * (1.f + erff(y * 0.70710678118654752f));
                out[((size_t)(b * 128 + s * 64 + cout)) * (HO * HO)
                    + oh * HO + ow] = y * wt;
            }
}

__global__ void __launch_bounds__(256, 2)
conv_all_kernel(const float* __restrict__ x, float* __restrict__ out) {
    extern __shared__ char smem[];
    unsigned sbase = smem_u32(smem);
    const int z = g_sched[blockIdx.y];          // heavy-first schedule
    const int e = g_selidx[z];
    const float* xb = x + (size_t)(z >> 1) * CIN * HW * HW;
    if (e == 0)      conv_body<0, 3, 1, 0 >(xb, out, z, smem, sbase);
    else if (e == 1) conv_body<1, 5, 2, 9 >(xb, out, z, smem, sbase);
    else if (e == 2) conv_body<2, 7, 3, 34>(xb, out, z, smem, sbase);
    else             conv_body<3, 9, 4, 83>(xb, out, z, smem, sbase);
}

// ---------------- launch: exactly 4 launches, conv is #4 (ncu capture slot) -----
extern "C" void kernel_launch(void* const* d_in, const int* in_sizes, int n_in,
                              void* d_out, int out_size) {
    (void)in_sizes; (void)n_in; (void)out_size;
    const float* x   = (const float*)d_in[0];
    const float* w0  = (const float*)d_in[1];
    const float* b0  = (const float*)d_in[2];
    const float* w1  = (const float*)d_in[3];
    const float* b1  = (const float*)d_in[4];
    const float* w2  = (const float*)d_in[5];
    const float* b2  = (const float*)d_in[6];
    const float* w3  = (const float*)d_in[7];
    const float* b3  = (const float*)d_in[8];
    const float* bns = (const float*)d_in[9];
    const float* bnb = (const float*)d_in[10];
    const float* bnm = (const float*)d_in[11];
    const float* bnv = (const float*)d_in[12];
    const float* gw  = (const float*)d_in[13];
    const float* gb  = (const float*)d_in[14];
    float* out = (float*)d_out;

    static int s_attr_set = 0;
    if (!s_attr_set) {
        cudaFuncSetAttribute(conv_all_kernel,
                             cudaFuncAttributeMaxDynamicSharedMemorySize,
                             CONV_SMEM);
        s_attr_set = 1;
    }

    pool_kernel<<<NB * CIN, 256>>>(x);                                   // #1
    wsplit_kernel<<<(164 * 4096 + 255) / 256, 256>>>(w0, w1, w2, w3);    // #2
    gatebn_kernel<<<1, 256>>>(gw, gb, bns, bnb, bnm, bnv,
                              b0, b1, b2, b3);                           // #3
    dim3 grid(128, NB * 2);   // oh x (b,slot heavy-first)
    conv_all_kernel<<<grid, 256, CONV_SMEM>>>(x, out);                   // #4
}

// round 17
// speedup vs baseline: 2.5079x; 1.0857x over previous
#include <cuda_runtime.h>
#include <cuda_fp16.h>
#include <math.h>

#define CIN 64
#define HW  256
#define HO  128
#define NB  16

// ---------------- device scratch (no allocations allowed) ----------------
__device__ float g_pooled[NB * CIN];
__device__ int   g_selidx[NB * 2];
__device__ float g_selwt [NB * 2];
__device__ int   g_sched [NB * 2];
__device__ float g_bnA[4 * 64];
__device__ float g_bnB[4 * 64];
// split weights: [split(2)][tapflat(164)][cout(64)][cin(64)] fp16
__device__ __align__(16) __half g_wS[2 * 164 * 4096];

// ---------------- launch #1: global average pool ----------------
__global__ void pool_kernel(const float* __restrict__ x) {
    __shared__ float red[256];
    int tid = threadIdx.x;
    const float4* xp = (const float4*)(x + (size_t)blockIdx.x * (HW * HW));
    float s = 0.f;
    for (int i = tid; i < HW * HW / 4; i += 256) {
        float4 v = xp[i];
        s += (v.x + v.y) + (v.z + v.w);
    }
    red[tid] = s;
    __syncthreads();
    for (int off = 128; off > 0; off >>= 1) {
        if (tid < off) red[tid] += red[tid + off];
        __syncthreads();
    }
    if (tid == 0) g_pooled[blockIdx.x] = red[0] * (1.f / (HW * HW));
}

// ---------------- launch #2: weight split to fp16 hi/lo ----------------
__global__ void wsplit_kernel(const float* __restrict__ w0, const float* __restrict__ w1,
                              const float* __restrict__ w2, const float* __restrict__ w3) {
    int i = blockIdx.x * 256 + threadIdx.x;
    if (i >= 164 * 4096) return;
    int cin  = i & 63;
    int cout = (i >> 6) & 63;
    int tapf = i >> 12;
    const float* w; int KK, kidx;
    if (tapf < 9)       { w = w0; KK = 9;  kidx = tapf; }
    else if (tapf < 34) { w = w1; KK = 25; kidx = tapf - 9; }
    else if (tapf < 83) { w = w2; KK = 49; kidx = tapf - 34; }
    else                { w = w3; KK = 81; kidx = tapf - 83; }
    float v = w[(cout * 64 + cin) * KK + kidx];
    __half hi = __float2half_rn(v);
    __half lo = __float2half_rn(v - __half2float(hi));
    g_wS[i] = hi;
    g_wS[671744 + i] = lo;
}

// ---------------- launch #3: gate + bn fold + schedule ----------------
__global__ void gatebn_kernel(const float* __restrict__ gw, const float* __restrict__ gb,
                              const float* __restrict__ sc, const float* __restrict__ bi,
                              const float* __restrict__ me, const float* __restrict__ va,
                              const float* __restrict__ b0, const float* __restrict__ b1,
                              const float* __restrict__ b2, const float* __restrict__ b3) {
    __shared__ int s_idx[NB * 2];
    int t = threadIdx.x;
    {
        const float* bb = (t < 64) ? b0 : (t < 128) ? b1 : (t < 192) ? b2 : b3;
        float inv = sc[t] * rsqrtf(va[t] + 1e-5f);
        g_bnA[t] = inv;
        g_bnB[t] = bb[t & 63] * inv + bi[t] - me[t] * inv;
    }
    if (t < NB) {
        int b = t;
        float lg[4];
        for (int e = 0; e < 4; ++e) {
            float s = gb[e];
            for (int c = 0; c < CIN; ++c) s += g_pooled[b * CIN + c] * gw[e * CIN + c];
            lg[e] = s;
        }
        float m = fmaxf(fmaxf(lg[0], lg[1]), fmaxf(lg[2], lg[3]));
        float p[4]; float Z = 0.f;
        for (int e = 0; e < 4; ++e) { p[e] = expf(lg[e] - m); Z += p[e]; }
        for (int e = 0; e < 4; ++e) p[e] /= Z;
        int i0 = 0;
        for (int e = 1; e < 4; ++e) if (p[e] > p[i0]) i0 = e;
        int i1 = -1;
        for (int e = 0; e < 4; ++e) {
            if (e == i0) continue;
            if (i1 < 0 || p[e] > p[i1]) i1 = e;
        }
        float den = p[i0] + p[i1] + 1e-8f;
        g_selidx[b * 2 + 0] = i0; g_selwt[b * 2 + 0] = p[i0] / den;
        g_selidx[b * 2 + 1] = i1; g_selwt[b * 2 + 1] = p[i1] / den;
        s_idx[b * 2 + 0] = i0;
        s_idx[b * 2 + 1] = i1;
    }
    __syncthreads();
    if (t == 0) {
        int n = 0;
        for (int e = 3; e >= 0; --e)
            for (int z = 0; z < NB * 2; ++z)
                if (s_idx[z] == e) g_sched[n++] = z;
    }
}

// ---------------- mma.sync helpers ----------------
__device__ __forceinline__ unsigned smem_u32(const void* p) {
    return (unsigned)__cvta_generic_to_shared(p);
}
__device__ __forceinline__ void sts128(unsigned a, unsigned r0, unsigned r1,
                                       unsigned r2, unsigned r3) {
    asm volatile("st.shared.v4.b32 [%0], {%1,%2,%3,%4};"
                 :: "r"(a), "r"(r0), "r"(r1), "r"(r2), "r"(r3) : "memory");
}
__device__ __forceinline__ void ldsm4(unsigned a, unsigned* r) {
    asm volatile("ldmatrix.sync.aligned.m8n8.x4.shared.b16 {%0,%1,%2,%3}, [%4];"
                 : "=r"(r[0]), "=r"(r[1]), "=r"(r[2]), "=r"(r[3]) : "r"(a));
}
__device__ __forceinline__ void mma16816(float* d, const unsigned* a, const unsigned* b) {
    asm volatile(
        "mma.sync.aligned.m16n8k16.row.col.f32.f16.f16.f32 "
        "{%0,%1,%2,%3}, {%4,%5,%6,%7}, {%8,%9}, {%0,%1,%2,%3};"
        : "+f"(d[0]), "+f"(d[1]), "+f"(d[2]), "+f"(d[3])
        : "r"(a[0]), "r"(a[1]), "r"(a[2]), "r"(a[3]), "r"(b[0]), "r"(b[1]));
}

// smem layout (144B rows, conflict-free LDSM):
//   rc: 2 oh-rows x [parity(2)][144 rows][144B] = 82944 fp16 (x, quantized).
//       rows 0..7 and 136..143 of each parity array are zero halos.
//   BS: single-buffer per-tap B tile [split2][64][144B] = 18432,
//       unioned with the 64x65 f32 transpose staging (16640).
#define RC_PAR   20736
#define RC_ROW   41472
#define SM_BS    82944
#define BS_SPLIT 9216
#define CONV_SMEM 101376

struct Bregs { uint4 h0, h1, l0, l1; };

__device__ __forceinline__ void ldgB(Bregs& r, int tapidx, int tid) {
    int n = tid >> 2, q = tid & 3;
    const uint4* sh = (const uint4*)(g_wS + (size_t)tapidx * 4096);
    const uint4* sl = (const uint4*)(g_wS + 671744 + (size_t)tapidx * 4096);
    int si = n * 8 + q * 2;
    r.h0 = __ldg(sh + si); r.h1 = __ldg(sh + si + 1);
    r.l0 = __ldg(sl + si); r.l1 = __ldg(sl + si + 1);
}
__device__ __forceinline__ void stsB(const Bregs& r, unsigned dst, int tid) {
    int n = tid >> 2, q = tid & 3;
    unsigned db = dst + n * 144 + q * 32;
    sts128(db,      r.h0.x, r.h0.y, r.h0.z, r.h0.w);
    sts128(db + 16, r.h1.x, r.h1.y, r.h1.z, r.h1.w);
    sts128(db + BS_SPLIT,      r.l0.x, r.l0.y, r.l0.z, r.l0.w);
    sts128(db + BS_SPLIT + 16, r.l1.x, r.l1.y, r.l1.z, r.l1.w);
}

// ---------------- launch #4: mma.sync fp16 implicit conv, M=256 (2 oh rows) ----
// CTA = (z, oh-pair). D[256 px x 64 cout]; B staged once per tap serves both rows.
// 8 warps = 4 (M strips of 64) x 2 (N halves of 32); per warp 4x4 m16n8 tiles.
template <int E, int K, int D, int TAPBASE>
__device__ void conv_body(const float* __restrict__ xb, float* __restrict__ out,
                          int z, char* smem, unsigned sbase) {
    const int tid = threadIdx.x, lane = tid & 31, wid = tid >> 5;
    const int wm = wid >> 1, wn = wid & 1;
    const int rcsel = wm >> 1;                   // which oh row this warp works on
    const int mlo   = 64 * (wm & 1);             // ow strip base within the row
    const int oh0 = blockIdx.x * 2;
    const int pad = D * (K - 1) / 2;
    const unsigned RCB = sbase, BSB = sbase + SM_BS;
    float* stg = (float*)(smem + SM_BS);

    // zero halo rows (phys 0..7, 136..143) in all 4 (row,parity) arrays
    for (int i = tid; i < 576; i += 256) {
        int c = i % 9;
        int rowi = i / 9;                         // 0..63
        int arr = rowi >> 4;                      // row*2+parity
        int r = rowi & 15;
        int phys = (r < 8) ? r : (128 + r);
        sts128(RCB + arr * RC_PAR + phys * 144 + c * 16, 0, 0, 0, 0);
    }

    float d[4][4][4];
#pragma unroll
    for (int mt = 0; mt < 4; ++mt)
#pragma unroll
        for (int nt = 0; nt < 4; ++nt)
#pragma unroll
            for (int c = 0; c < 4; ++c) d[mt][nt][c] = 0.f;

    // ldmatrix lane mappings
    const int row16 = lane & 15;
    const int koffA = (lane >> 4) * 16;
    const int bsel = lane >> 3, brow = lane & 7;
    const int bnt = bsel >> 1;
    const int bko = (bsel & 1) * 16;

    Bregs breg;

#pragma unroll 1
    for (int kh = 0; kh < K; ++kh) {
        int xra = 2 * oh0 - pad + D * kh;         // input row for oh0; oh0+1 uses xra+2
        if (xra < -2 || xra >= HW) continue;      // both rows OOB -> whole tap row zero

        // ---- rebuild both row caches ----
#pragma unroll 1
        for (int r = 0; r < 2; ++r) {
            int xr = xra + 2 * r;
            unsigned RCrow = RCB + r * RC_ROW;
            if ((unsigned)xr < (unsigned)HW) {
#pragma unroll 1
                for (int slab = 0; slab < 4; ++slab) {
                    __syncthreads();              // prior MMA/stg reads done
                    {
                        int cin = tid >> 2, q = tid & 3;
                        const float4* src = (const float4*)(xb + (size_t)cin * (HW * HW)
                                                            + xr * HW + slab * 64 + q * 16);
                        float4 v0 = src[0], v1 = src[1], v2 = src[2], v3 = src[3];
                        float* dp = stg + cin * 65 + q * 16;
                        dp[0]=v0.x; dp[1]=v0.y; dp[2]=v0.z; dp[3]=v0.w;
                        dp[4]=v1.x; dp[5]=v1.y; dp[6]=v1.z; dp[7]=v1.w;
                        dp[8]=v2.x; dp[9]=v2.y; dp[10]=v2.z; dp[11]=v2.w;
                        dp[12]=v3.x; dp[13]=v3.y; dp[14]=v3.z; dp[15]=v3.w;
                    }
                    __syncthreads();
                    {
                        int col = tid >> 2, q = tid & 3;
                        int p = slab * 64 + col;
                        int pr = p & 1;
                        int phys = (p >> 1) + 8;
                        unsigned hp[8];
#pragma unroll
                        for (int k = 0; k < 8; ++k) {
                            __half h0 = __float2half_rn(stg[(q * 16 + 2 * k) * 65 + col]);
                            __half h1 = __float2half_rn(stg[(q * 16 + 2 * k + 1) * 65 + col]);
                            hp[k] = (unsigned)*(unsigned short*)&h0
                                  | ((unsigned)*(unsigned short*)&h1 << 16);
                        }
                        unsigned ah = RCrow + pr * RC_PAR + phys * 144 + q * 32;
                        sts128(ah,      hp[0], hp[1], hp[2], hp[3]);
                        sts128(ah + 16, hp[4], hp[5], hp[6], hp[7]);
                    }
                }
            } else {
                __syncthreads();                  // prior MMA reads of rc done
                // zero the 128 data rows in both parity arrays of this row cache
                for (int i = tid; i < 2048; i += 256) {  // 2 par * 128 rows * 8 chunks
                    int c = i & 7;
                    int rowi = i >> 3;             // 0..255
                    int pr = rowi >> 7;
                    int phys = (rowi & 127) + 8;
                    sts128(RCrow + pr * RC_PAR + phys * 144 + c * 16, 0, 0, 0, 0);
                }
            }
        }
        __syncthreads();                          // row caches visible

        ldgB(breg, TAPBASE + kh * K, tid);        // prefetch first tap's B

        // ---- taps of this kh: single B buffer, register prefetch ----
#pragma unroll 1
        for (int kw = 0; kw < K; ++kw) {
            stsB(breg, BSB, tid);
            __syncthreads();                      // B staged; rc stable
            if (kw + 1 < K) ldgB(breg, TAPBASE + kh * K + kw + 1, tid);

            const int off = D * kw - pad;
            const int pr = off & 1;
            const int ibase = ((off - pr) >> 1) + 8;
            const unsigned ABase = RCB + rcsel * RC_ROW + pr * RC_PAR;

#pragma unroll 1
            for (int kc = 0; kc < 4; ++kc) {
                unsigned aH[4][4], bf[4][2];
#pragma unroll
                for (int mt = 0; mt < 4; ++mt) {
                    int m = mlo + 16 * mt + row16;
                    ldsm4(ABase + (unsigned)(m + ibase) * 144 + koffA + kc * 32, aH[mt]);
                }
                // hi split
#pragma unroll
                for (int np = 0; np < 2; ++np) {
                    int n = 32 * wn + (2 * np + bnt) * 8 + brow;
                    unsigned t[4];
                    ldsm4(BSB + (unsigned)n * 144 + bko + kc * 32, t);
                    bf[2*np][0]=t[0]; bf[2*np][1]=t[1];
                    bf[2*np+1][0]=t[2]; bf[2*np+1][1]=t[3];
                }
#pragma unroll
                for (int mt = 0; mt < 4; ++mt)
#pragma unroll
                    for (int nt = 0; nt < 4; ++nt)
                        mma16816(d[mt][nt], aH[mt], bf[nt]);
                // lo split
#pragma unroll
                for (int np = 0; np < 2; ++np) {
                    int n = 32 * wn + (2 * np + bnt) * 8 + brow;
                    unsigned t[4];
                    ldsm4(BSB + BS_SPLIT + (unsigned)n * 144 + bko + kc * 32, t);
                    bf[2*np][0]=t[0]; bf[2*np][1]=t[1];
                    bf[2*np+1][0]=t[2]; bf[2*np+1][1]=t[3];
                }
#pragma unroll
                for (int mt = 0; mt < 4; ++mt)
#pragma unroll
                    for (int nt = 0; nt < 4; ++nt)
                        mma16816(d[mt][nt], aH[mt], bf[nt]);
            }
            __syncthreads();                      // B reads done before next STS
        }
    }

    // ---- epilogue: BN fold + exact GELU + gate weight ----
    const float wt = g_selwt[z];
    const int b = z >> 1, s = z & 1;
    const int oh = oh0 + rcsel;
#pragma unroll
    for (int mt = 0; mt < 4; ++mt)
#pragma unroll
        for (int nt = 0; nt < 4; ++nt)
#pragma unroll
            for (int c = 0; c < 4; ++c) {
                int ow = mlo + 16 * mt + (lane >> 2) + ((c >= 2) ? 8 : 0);
                int cout = 32 * wn + 8 * nt + (lane & 3) * 2 + (c & 1);
                float v = d[mt][nt][c];
                float y = v * g_bnA[E * 64 + cout] + g_bnB[E * 64 + cout];
                y = 0.5f * y * (1.f + erff(y * 0.70710678118654752f));
                out[((size_t)(b * 128 + s * 64 + cout)) * (HO * HO)
                    + oh * HO + ow] = y * wt;
            }
}

__global__ void __launch_bounds__(256, 2)
conv_all_kernel(const float* __restrict__ x, float* __restrict__ out) {
    extern __shared__ char smem[];
    unsigned sbase = smem_u32(smem);
    const int z = g_sched[blockIdx.y];
    const int e = g_selidx[z];
    const float* xb = x + (size_t)(z >> 1) * CIN * HW * HW;
    if (e == 0)      conv_body<0, 3, 1, 0 >(xb, out, z, smem, sbase);
    else if (e == 1) conv_body<1, 5, 2, 9 >(xb, out, z, smem, sbase);
    else if (e == 2) conv_body<2, 7, 3, 34>(xb, out, z, smem, sbase);
    else             conv_body<3, 9, 4, 83>(xb, out, z, smem, sbase);
}

// ---------------- launch: exactly 4 launches, conv is #4 (ncu capture slot) -----
extern "C" void kernel_launch(void* const* d_in, const int* in_sizes, int n_in,
                              void* d_out, int out_size) {
    (void)in_sizes; (void)n_in; (void)out_size;
    const float* x   = (const float*)d_in[0];
    const float* w0  = (const float*)d_in[1];
    const float* b0  = (const float*)d_in[2];
    const float* w1  = (const float*)d_in[3];
    const float* b1  = (const float*)d_in[4];
    const float* w2  = (const float*)d_in[5];
    const float* b2  = (const float*)d_in[6];
    const float* w3  = (const float*)d_in[7];
    const float* b3  = (const float*)d_in[8];
    const float* bns = (const float*)d_in[9];
    const float* bnb = (const float*)d_in[10];
    const float* bnm = (const float*)d_in[11];
    const float* bnv = (const float*)d_in[12];
    const float* gw  = (const float*)d_in[13];
    const float* gb  = (const float*)d_in[14];
    float* out = (float*)d_out;

    static int s_attr_set = 0;
    if (!s_attr_set) {
        cudaFuncSetAttribute(conv_all_kernel,
                             cudaFuncAttributeMaxDynamicSharedMemorySize,
                             CONV_SMEM);
        s_attr_set = 1;
    }

    pool_kernel<<<NB * CIN, 256>>>(x);                                   // #1
    wsplit_kernel<<<(164 * 4096 + 255) / 256, 256>>>(w0, w1, w2, w3);    // #2
    gatebn_kernel<<<1, 256>>>(gw, gb, bns, bnb, bnm, bnv,
                              b0, b1, b2, b3);                           // #3
    dim3 grid(64, NB * 2);   // oh-pairs x (b,slot heavy-first)
    conv_all_kernel<<<grid, 256, CONV_SMEM>>>(x, out);                   // #4
}